// round 12
// baseline (speedup 1.0000x reference)
#include <cuda_runtime.h>
#include <cstdint>

#define HSZ   512
#define ISZ   256
#define BSZ   64
#define NBLK  128
#define NTHR  256
#define WHD_STR 1028   // 1024 dup floats + 4 pad
#define WID_STR 516
#define PSTR    68     // partial row stride
#define EPSBN 1e-5f

// smem layout (floats)
#define OFF_WHD  0
#define OFF_WID  (OFF_WHD + 16*WHD_STR)        // 16448
#define OFF_ST   (OFF_WID + 16*WID_STR)        // 24704 (4 slots x 4096 floats = 64KB)
#define OFF_P    (OFF_ST + 4*4096)             // 41088 (8 warps x 16 x 68 — single partial buffer, two passes)
#define OFF_SG   (OFF_P + 8*16*PSTR)           // 49792
#define OFF_CST  (OFF_SG + 16*64)              // 50816
#define SMEM_FLOATS (OFF_CST + 96)             // 50912
#define SMEM_BYTES  (SMEM_FLOATS*4)            // 203648 B ≈ 199 KB (< 227KB cap)

#define SLOT_BYTES 16384u

__device__ float g_h[2][HSZ*BSZ];
__device__ unsigned g_arrive;
__device__ unsigned g_release;

typedef unsigned long long ull;

__device__ __forceinline__ void unpack2(ull v, float &lo, float &hi){
    asm("mov.b64 {%0, %1}, %2;" : "=f"(lo), "=f"(hi) : "l"(v));
}
__device__ __forceinline__ void ffma2(ull &acc, ull a, ull b){
    asm("fma.rn.f32x2 %0, %1, %2, %0;" : "+l"(acc) : "l"(a), "l"(b));
}
__device__ __forceinline__ void addf2(ull &acc, ull a){
    asm("add.rn.f32x2 %0, %0, %1;" : "+l"(acc) : "l"(a));
}
__device__ __forceinline__ void cp16(uint32_t dst, const void* src){
    asm volatile("cp.async.cg.shared.global [%0], [%1], 16;" :: "r"(dst), "l"(src));
}
__device__ __forceinline__ float sigm(float x){
    return 1.0f / (1.0f + __expf(-x));
}

// 8-k slice of one chunk: thread does 4 rows x 8 cols (16 acc f32x2). (unchanged from R11)
__device__ __forceinline__ void gemm_slice(const float* __restrict__ st,
                                           const float* __restrict__ wb, int wstr,
                                           int c0, ull* __restrict__ acc)
{
    #pragma unroll
    for (int g = 0; g < 2; g++){
        ulonglong2 w0l = *(const ulonglong2*)(wb + 0*4*wstr + g*8);
        ulonglong2 w0h = *(const ulonglong2*)(wb + 0*4*wstr + g*8 + 4);
        ulonglong2 w1l = *(const ulonglong2*)(wb + 1*4*wstr + g*8);
        ulonglong2 w1h = *(const ulonglong2*)(wb + 1*4*wstr + g*8 + 4);
        ulonglong2 w2l = *(const ulonglong2*)(wb + 2*4*wstr + g*8);
        ulonglong2 w2h = *(const ulonglong2*)(wb + 2*4*wstr + g*8 + 4);
        ulonglong2 w3l = *(const ulonglong2*)(wb + 3*4*wstr + g*8);
        ulonglong2 w3h = *(const ulonglong2*)(wb + 3*4*wstr + g*8 + 4);
        #pragma unroll
        for (int kk = 0; kk < 4; kk++){
            const float* sp = st + (g*4 + kk)*64 + c0;
            ulonglong2 sa = *(const ulonglong2*)(sp);
            ulonglong2 sb = *(const ulonglong2*)(sp + 32);
            ull w0 = (kk==0)?w0l.x:(kk==1)?w0l.y:(kk==2)?w0h.x:w0h.y;
            ull w1 = (kk==0)?w1l.x:(kk==1)?w1l.y:(kk==2)?w1h.x:w1h.y;
            ull w2 = (kk==0)?w2l.x:(kk==1)?w2l.y:(kk==2)?w2h.x:w2h.y;
            ull w3 = (kk==0)?w3l.x:(kk==1)?w3l.y:(kk==2)?w3h.x:w3h.y;
            ffma2(acc[ 0], w0, sa.x); ffma2(acc[ 1], w0, sa.y);
            ffma2(acc[ 2], w0, sb.x); ffma2(acc[ 3], w0, sb.y);
            ffma2(acc[ 4], w1, sa.x); ffma2(acc[ 5], w1, sa.y);
            ffma2(acc[ 6], w1, sb.x); ffma2(acc[ 7], w1, sb.y);
            ffma2(acc[ 8], w2, sa.x); ffma2(acc[ 9], w2, sa.y);
            ffma2(acc[10], w2, sb.x); ffma2(acc[11], w2, sb.y);
            ffma2(acc[12], w3, sa.x); ffma2(acc[13], w3, sa.y);
            ffma2(acc[14], w3, sb.x); ffma2(acc[15], w3, sb.y);
        }
    }
}

extern "C" __global__ void __launch_bounds__(NTHR, 1)
lstm_bn_kernel(const float* __restrict__ x,
               const float* __restrict__ Wih,
               const float* __restrict__ Whh,
               const float* __restrict__ bias,
               const float* __restrict__ gIH, const float* __restrict__ bIH,
               const float* __restrict__ gHH, const float* __restrict__ bHH,
               const float* __restrict__ gC,  const float* __restrict__ bC,
               float* __restrict__ out, int T)
{
    extern __shared__ float sm[];
    float* whd    = sm + OFF_WHD;
    float* wid    = sm + OFF_WID;
    float* stage  = sm + OFF_ST;
    float* pP     = sm + OFF_P;
    float* sg     = sm + OFF_SG;
    float* ghh_s  = sm + OFF_CST;
    float* bhh_s  = ghh_s + 16;
    float* gih_s  = bhh_s + 16;
    float* bih_s  = gih_s + 16;
    float* bias_s = bih_s + 16;
    float* gc_s   = bias_s + 16;
    float* bc_s   = gc_s + 4;

    const int tid  = threadIdx.x;
    const int blk  = blockIdx.x;
    const int w    = tid >> 5;          // warp 0..7 = k-slice within each chunk
    const int lane = tid & 31;
    const int rowg = lane >> 3;         // rows {rowg, rowg+4, rowg+8, rowg+12}
    const int colg = lane & 7;          // cols {colg*4..+3} ∪ {+32..+35}
    const int c0   = colg * 4;

    // ---- preload weights, DUPLICATED
    for (int idx = tid; idx < 16*HSZ; idx += NTHR){
        int l = idx >> 9, k = idx & 511;
        int grow = (l >> 2) * HSZ + blk*4 + (l & 3);
        float v = Whh[(size_t)grow * HSZ + k];
        whd[l*WHD_STR + 2*k]     = v;
        whd[l*WHD_STR + 2*k + 1] = v;
    }
    for (int idx = tid; idx < 16*ISZ; idx += NTHR){
        int l = idx >> 8, k = idx & 255;
        int grow = (l >> 2) * HSZ + blk*4 + (l & 3);
        float v = Wih[(size_t)grow * ISZ + k];
        wid[l*WID_STR + 2*k]     = v;
        wid[l*WID_STR + 2*k + 1] = v;
    }
    if (tid < 16){
        int grow = (tid >> 2) * HSZ + blk*4 + (tid & 3);
        ghh_s[tid] = gHH[grow]; bhh_s[tid] = bHH[grow];
        gih_s[tid] = gIH[grow]; bih_s[tid] = bIH[grow];
        bias_s[tid] = bias[grow];
    }
    if (tid < 4){ gc_s[tid] = gC[blk*4 + tid]; bc_s[tid] = bC[blk*4 + tid]; }

    g_h[0][blk * NTHR + tid] = 0.f;
    __syncthreads();

    unsigned gen0 = 0, my_gen = 0;
    if (tid == 0) gen0 = *((volatile unsigned*)&g_release);

    auto gridsync = [&](){
        __syncthreads();
        if (tid == 0){
            my_gen++;
            __threadfence();
            unsigned a = atomicAdd(&g_arrive, 1u);
            if (a == (unsigned)(NBLK - 1)){
                atomicExch(&g_arrive, 0u);
                __threadfence();
                atomicAdd(&g_release, 1u);
            } else {
                while ( (*((volatile unsigned*)&g_release)) - gen0 < my_gen ) { }
            }
        }
        __syncthreads();
    };

    const uint32_t stBase = (uint32_t)__cvta_generic_to_shared(stage);
    const float inv64 = 1.0f / 64.0f;
    float creg0 = 0.f, creg1 = 0.f;

    const float* whb = whd + rowg*WHD_STR + w*16;   // + chunk*128 per chunk
    const float* wib = wid + rowg*WID_STR + w*16;

    // warp-private slice prefetch: warp w copies its 8 k-rows (512 floats) of a chunk
    const uint32_t dstWarp = stBase + (uint32_t)w*2048u + (uint32_t)lane*16u;

    // ---- prime: x chunks 0..3 of step 0 (items 0..3) into slots 0..3
    {
        #pragma unroll
        for (int i = 0; i < 4; i++){
            const float* src = x + i*4096 + w*512 + lane*4;
            uint32_t d = dstWarp + (uint32_t)i*SLOT_BYTES;
            #pragma unroll
            for (int p = 0; p < 4; p++)
                cp16(d + (uint32_t)p*512u, src + p*128);
            asm volatile("cp.async.commit_group;");
        }
    }

    gridsync();   // h buffer zeroed everywhere before step 0

    for (int t = 0; t < T; t++){
        const float* hrd = g_h[t & 1];
        float*       hwr = g_h[(t + 1) & 1];
        const float* xnx = x + (size_t)((t+1 < T) ? (t+1) : (T-1)) * (ISZ*BSZ);

        ull accA[16], accB[16];
        #pragma unroll
        for (int i = 0; i < 16; i++){ accA[i] = 0; accB[i] = 0; }

        // items 0..3 = x chunks 0..3 (ih), items 4..11 = h chunks 0..7 (hh).
        // Uniform pipeline: wait oldest, compute item m, issue item m+4 into slot m&3.
        #pragma unroll 4
        for (int m = 0; m < 12; m++){
            asm volatile("cp.async.wait_group 3;");
            __syncwarp();
            const float* st = stage + (m & 3)*4096 + w*512;
            if (m < 4) gemm_slice(st, wib + m*128,     WID_STR, c0, accB);
            else       gemm_slice(st, whb + (m-4)*128, WHD_STR, c0, accA);

            // issue item m+4 (m<8: h chunk m, current step; m>=8: x chunk m-8 of next step)
            const float* src = (m < 8) ? (hrd + m*4096 + w*512 + lane*4)
                                       : (xnx + (m-8)*4096 + w*512 + lane*4);
            uint32_t d = dstWarp + (uint32_t)(m & 3)*SLOT_BYTES;
            #pragma unroll
            for (int p = 0; p < 4; p++)
                cp16(d + (uint32_t)p*512u, src + p*128);
            asm volatile("cp.async.commit_group;");
        }

        // ---- pass A: write hh partials, reduce
        {
            float* pp = pP + w*(16*PSTR);
            #pragma unroll
            for (int j = 0; j < 4; j++){
                int rr2 = rowg + j*4;
                *(ulonglong2*)(pp + rr2*PSTR + c0)      = make_ulonglong2(accA[j*4+0], accA[j*4+1]);
                *(ulonglong2*)(pp + rr2*PSTR + c0 + 32) = make_ulonglong2(accA[j*4+2], accA[j*4+3]);
            }
        }
        __syncthreads();

        const int rr = tid >> 4, c4 = (tid & 15) * 4;
        float vA[4], vB[4];
        {
            ulonglong2 s = *(const ulonglong2*)(pP + rr*PSTR + c4);
            ull ax = s.x, ay = s.y;
            #pragma unroll
            for (int ww = 1; ww < 8; ww++){
                ulonglong2 q = *(const ulonglong2*)(pP + ww*(16*PSTR) + rr*PSTR + c4);
                addf2(ax, q.x); addf2(ay, q.y);
            }
            unpack2(ax, vA[0], vA[1]); unpack2(ay, vA[2], vA[3]);
        }
        __syncthreads();   // WAR: reuse buffer for pass B

        // ---- pass B: write ih partials, reduce
        {
            float* pp = pP + w*(16*PSTR);
            #pragma unroll
            for (int j = 0; j < 4; j++){
                int rr2 = rowg + j*4;
                *(ulonglong2*)(pp + rr2*PSTR + c0)      = make_ulonglong2(accB[j*4+0], accB[j*4+1]);
                *(ulonglong2*)(pp + rr2*PSTR + c0 + 32) = make_ulonglong2(accB[j*4+2], accB[j*4+3]);
            }
        }
        __syncthreads();
        {
            ulonglong2 s = *(const ulonglong2*)(pP + rr*PSTR + c4);
            ull bx = s.x, by = s.y;
            #pragma unroll
            for (int ww = 1; ww < 8; ww++){
                ulonglong2 q = *(const ulonglong2*)(pP + ww*(16*PSTR) + rr*PSTR + c4);
                addf2(bx, q.x); addf2(by, q.y);
            }
            unpack2(bx, vB[0], vB[1]); unpack2(by, vB[2], vB[3]);
        }

        // ---- per-gate-row batchnorm (thread owns row rr, cols c4..c4+3)
        {
            float sA = vA[0]+vA[1]+vA[2]+vA[3];
            float qA = vA[0]*vA[0]+vA[1]*vA[1]+vA[2]*vA[2]+vA[3]*vA[3];
            float sB = vB[0]+vB[1]+vB[2]+vB[3];
            float qB = vB[0]*vB[0]+vB[1]*vB[1]+vB[2]*vB[2]+vB[3]*vB[3];
            #pragma unroll
            for (int off = 1; off < 16; off <<= 1){
                sA += __shfl_xor_sync(0xffffffffu, sA, off);
                qA += __shfl_xor_sync(0xffffffffu, qA, off);
                sB += __shfl_xor_sync(0xffffffffu, sB, off);
                qB += __shfl_xor_sync(0xffffffffu, qB, off);
            }
            float muA = sA*inv64, muB = sB*inv64;
            float rsA = rsqrtf(qA*inv64 - muA*muA + EPSBN);
            float rsB = rsqrtf(qB*inv64 - muB*muB + EPSBN);
            float ga = ghh_s[rr]*rsA, gb = gih_s[rr]*rsB;
            float cadd = bhh_s[rr] + bih_s[rr] + bias_s[rr] - muA*ga - muB*gb;
            #pragma unroll
            for (int j = 0; j < 4; j++)
                sg[rr*64 + c4 + j] = fmaf(vA[j], ga, fmaf(vB[j], gb, cadd));
        }
        __syncthreads();

        // ---- phase B: gates + cell + c-BN + h (warps 0-3; warp w owns h-row blk*4+w)
        if (w < 4){
            float iv0 = sg[( 0 + w)*64 + lane], iv1 = sg[( 0 + w)*64 + lane + 32];
            float fv0 = sg[( 4 + w)*64 + lane], fv1 = sg[( 4 + w)*64 + lane + 32];
            float gv0 = sg[( 8 + w)*64 + lane], gv1 = sg[( 8 + w)*64 + lane + 32];
            float ov0 = sg[(12 + w)*64 + lane], ov1 = sg[(12 + w)*64 + lane + 32];

            creg0 = sigm(fv0)*creg0 + sigm(iv0)*tanhf(gv0);
            creg1 = sigm(fv1)*creg1 + sigm(iv1)*tanhf(gv1);

            float sc = creg0 + creg1;
            float qc = creg0*creg0 + creg1*creg1;
            #pragma unroll
            for (int off = 16; off >= 1; off >>= 1){
                sc += __shfl_xor_sync(0xffffffffu, sc, off);
                qc += __shfl_xor_sync(0xffffffffu, qc, off);
            }
            float mu = sc*inv64;
            float rs = rsqrtf(qc*inv64 - mu*mu + EPSBN);
            float gcv = gc_s[w]*rs;
            float bcv = bc_s[w] - mu*gcv;
            float h0v = sigm(ov0) * tanhf(fmaf(creg0, gcv, bcv));
            float h1v = sigm(ov1) * tanhf(fmaf(creg1, gcv, bcv));

            int rowg2 = blk*4 + w;
            hwr[rowg2*64 + lane]      = h0v;
            hwr[rowg2*64 + lane + 32] = h1v;
            float* op = out + (size_t)t * (HSZ*BSZ) + rowg2*64;
            op[lane]      = h0v;
            op[lane + 32] = h1v;
        }

        gridsync();   // h visible chip-wide before next step's h items are consumed
    }
}

extern "C" void kernel_launch(void* const* d_in, const int* in_sizes, int n_in,
                              void* d_out, int out_size)
{
    const float* x    = (const float*)d_in[0];
    const float* Wih  = (const float*)d_in[1];
    const float* Whh  = (const float*)d_in[2];
    const float* bias = (const float*)d_in[3];
    const float* gIH  = (const float*)d_in[4];
    const float* bIH  = (const float*)d_in[5];
    const float* gHH  = (const float*)d_in[6];
    const float* bHH  = (const float*)d_in[7];
    const float* gC   = (const float*)d_in[8];
    const float* bC   = (const float*)d_in[9];
    float* out = (float*)d_out;

    int T = in_sizes[0] / (ISZ * BSZ);   // 2048

    cudaFuncSetAttribute(lstm_bn_kernel,
                         cudaFuncAttributeMaxDynamicSharedMemorySize, SMEM_BYTES);
    lstm_bn_kernel<<<NBLK, NTHR, SMEM_BYTES>>>(x, Wih, Whh, bias,
                                               gIH, bIH, gHH, bHH, gC, bC,
                                               out, T);
}

// round 13
// speedup vs baseline: 1.0212x; 1.0212x over previous
#include <cuda_runtime.h>
#include <cstdint>

#define HSZ   512
#define ISZ   256
#define BSZ   64
#define NBLK  128
#define NTHR  256
#define WHD_STR 1028   // 1024 dup floats + 4 pad
#define WID_STR 516
#define PSTR    68     // partial row stride
#define EPSBN 1e-5f

// smem layout (floats)
#define OFF_WHD  0
#define OFF_WID  (OFF_WHD + 16*WHD_STR)        // 16448
#define OFF_ST   (OFF_WID + 16*WID_STR)        // 24704 (6 slots x 4096 floats = 96KB; slots 2..4 reused for partials in tail)
#define OFF_SG   (OFF_ST + 6*4096)             // 49280
#define OFF_CST  (OFF_SG + 16*64)              // 50304
#define SMEM_FLOATS (OFF_CST + 96)
#define SMEM_BYTES  (SMEM_FLOATS*4)            // ~197 KB (< 227KB cap)

#define SLOT_BYTES 16384u

__device__ float g_h[2][HSZ*BSZ];
__device__ unsigned g_arrive;
__device__ unsigned g_release;

typedef unsigned long long ull;

__device__ __forceinline__ void unpack2(ull v, float &lo, float &hi){
    asm("mov.b64 {%0, %1}, %2;" : "=f"(lo), "=f"(hi) : "l"(v));
}
__device__ __forceinline__ void ffma2(ull &acc, ull a, ull b){
    asm("fma.rn.f32x2 %0, %1, %2, %0;" : "+l"(acc) : "l"(a), "l"(b));
}
__device__ __forceinline__ void addf2(ull &acc, ull a){
    asm("add.rn.f32x2 %0, %0, %1;" : "+l"(acc) : "l"(a));
}
__device__ __forceinline__ void cp16(uint32_t dst, const void* src){
    asm volatile("cp.async.cg.shared.global [%0], [%1], 16;" :: "r"(dst), "l"(src));
}
__device__ __forceinline__ float sigm(float x){
    return 1.0f / (1.0f + __expf(-x));
}

// 8-k slice of one chunk: thread does 4 rows x 8 cols (16 acc f32x2). (unchanged from R11)
__device__ __forceinline__ void gemm_slice(const float* __restrict__ st,
                                           const float* __restrict__ wb, int wstr,
                                           int c0, ull* __restrict__ acc)
{
    #pragma unroll
    for (int g = 0; g < 2; g++){
        ulonglong2 w0l = *(const ulonglong2*)(wb + 0*4*wstr + g*8);
        ulonglong2 w0h = *(const ulonglong2*)(wb + 0*4*wstr + g*8 + 4);
        ulonglong2 w1l = *(const ulonglong2*)(wb + 1*4*wstr + g*8);
        ulonglong2 w1h = *(const ulonglong2*)(wb + 1*4*wstr + g*8 + 4);
        ulonglong2 w2l = *(const ulonglong2*)(wb + 2*4*wstr + g*8);
        ulonglong2 w2h = *(const ulonglong2*)(wb + 2*4*wstr + g*8 + 4);
        ulonglong2 w3l = *(const ulonglong2*)(wb + 3*4*wstr + g*8);
        ulonglong2 w3h = *(const ulonglong2*)(wb + 3*4*wstr + g*8 + 4);
        #pragma unroll
        for (int kk = 0; kk < 4; kk++){
            const float* sp = st + (g*4 + kk)*64 + c0;
            ulonglong2 sa = *(const ulonglong2*)(sp);
            ulonglong2 sb = *(const ulonglong2*)(sp + 32);
            ull w0 = (kk==0)?w0l.x:(kk==1)?w0l.y:(kk==2)?w0h.x:w0h.y;
            ull w1 = (kk==0)?w1l.x:(kk==1)?w1l.y:(kk==2)?w1h.x:w1h.y;
            ull w2 = (kk==0)?w2l.x:(kk==1)?w2l.y:(kk==2)?w2h.x:w2h.y;
            ull w3 = (kk==0)?w3l.x:(kk==1)?w3l.y:(kk==2)?w3h.x:w3h.y;
            ffma2(acc[ 0], w0, sa.x); ffma2(acc[ 1], w0, sa.y);
            ffma2(acc[ 2], w0, sb.x); ffma2(acc[ 3], w0, sb.y);
            ffma2(acc[ 4], w1, sa.x); ffma2(acc[ 5], w1, sa.y);
            ffma2(acc[ 6], w1, sb.x); ffma2(acc[ 7], w1, sb.y);
            ffma2(acc[ 8], w2, sa.x); ffma2(acc[ 9], w2, sa.y);
            ffma2(acc[10], w2, sb.x); ffma2(acc[11], w2, sb.y);
            ffma2(acc[12], w3, sa.x); ffma2(acc[13], w3, sa.y);
            ffma2(acc[14], w3, sb.x); ffma2(acc[15], w3, sb.y);
        }
    }
}

extern "C" __global__ void __launch_bounds__(NTHR, 1)
lstm_bn_kernel(const float* __restrict__ x,
               const float* __restrict__ Wih,
               const float* __restrict__ Whh,
               const float* __restrict__ bias,
               const float* __restrict__ gIH, const float* __restrict__ bIH,
               const float* __restrict__ gHH, const float* __restrict__ bHH,
               const float* __restrict__ gC,  const float* __restrict__ bC,
               float* __restrict__ out, int T)
{
    extern __shared__ float sm[];
    float* whd    = sm + OFF_WHD;
    float* wid    = sm + OFF_WID;
    float* stage  = sm + OFF_ST;
    float* sg     = sm + OFF_SG;
    float* ghh_s  = sm + OFF_CST;
    float* bhh_s  = ghh_s + 16;
    float* gih_s  = bhh_s + 16;
    float* bih_s  = gih_s + 16;
    float* bias_s = bih_s + 16;
    float* gc_s   = bias_s + 16;
    float* bc_s   = gc_s + 4;

    const int tid  = threadIdx.x;
    const int blk  = blockIdx.x;
    const int w    = tid >> 5;
    const int lane = tid & 31;
    const int rowg = lane >> 3;
    const int colg = lane & 7;
    const int c0   = colg * 4;

    // ---- preload weights, DUPLICATED
    for (int idx = tid; idx < 16*HSZ; idx += NTHR){
        int l = idx >> 9, k = idx & 511;
        int grow = (l >> 2) * HSZ + blk*4 + (l & 3);
        float v = Whh[(size_t)grow * HSZ + k];
        whd[l*WHD_STR + 2*k]     = v;
        whd[l*WHD_STR + 2*k + 1] = v;
    }
    for (int idx = tid; idx < 16*ISZ; idx += NTHR){
        int l = idx >> 8, k = idx & 255;
        int grow = (l >> 2) * HSZ + blk*4 + (l & 3);
        float v = Wih[(size_t)grow * ISZ + k];
        wid[l*WID_STR + 2*k]     = v;
        wid[l*WID_STR + 2*k + 1] = v;
    }
    if (tid < 16){
        int grow = (tid >> 2) * HSZ + blk*4 + (tid & 3);
        ghh_s[tid] = gHH[grow]; bhh_s[tid] = bHH[grow];
        gih_s[tid] = gIH[grow]; bih_s[tid] = bIH[grow];
        bias_s[tid] = bias[grow];
    }
    if (tid < 4){ gc_s[tid] = gC[blk*4 + tid]; bc_s[tid] = bC[blk*4 + tid]; }

    g_h[0][blk * NTHR + tid] = 0.f;
    __syncthreads();

    unsigned gen0 = 0, my_gen = 0;
    if (tid == 0) gen0 = *((volatile unsigned*)&g_release);

    auto gridsync = [&](){
        __syncthreads();
        if (tid == 0){
            my_gen++;
            __threadfence();
            unsigned a = atomicAdd(&g_arrive, 1u);
            if (a == (unsigned)(NBLK - 1)){
                atomicExch(&g_arrive, 0u);
                __threadfence();
                atomicAdd(&g_release, 1u);
            } else {
                while ( (*((volatile unsigned*)&g_release)) - gen0 < my_gen ) { }
            }
        }
        __syncthreads();
    };

    const uint32_t stBase = (uint32_t)__cvta_generic_to_shared(stage);
    const float inv64 = 1.0f / 64.0f;
    float creg0 = 0.f, creg1 = 0.f;

    const float* whb = whd + rowg*WHD_STR + w*16;
    const float* wib = wid + rowg*WID_STR + w*16;

    // block-wide issue of one 2-chunk group (32KB): 8 cp16/thread + commit
    auto issue_pair = [&](const float* cA, const float* cB, int sa, int sb){
        uint32_t dA = stBase + (uint32_t)sa * SLOT_BYTES;
        uint32_t dB = stBase + (uint32_t)sb * SLOT_BYTES;
        #pragma unroll
        for (int j = 0; j < 4; j++){
            cp16(dA + (uint32_t)(tid + j*256)*16u, cA + (tid + j*256)*4);
            cp16(dB + (uint32_t)(tid + j*256)*16u, cB + (tid + j*256)*4);
        }
        asm volatile("cp.async.commit_group;");
    };

    // ---- prime: x chunks 0,1 of step 0 into slots 0,1 (the steady-state "next-x" group)
    issue_pair(x, x + 4096, 0, 1);

    gridsync();   // h buffer zeroed everywhere before step 0

    for (int t = 0; t < T; t++){
        const float* hrd = g_h[t & 1];
        float*       hwr = g_h[(t + 1) & 1];
        const float* xt  = x + (size_t)t * (ISZ*BSZ);
        const float* xnx = x + (size_t)((t+1 < T) ? (t+1) : (T-1)) * (ISZ*BSZ);

        ull accA[16], accB[16];
        #pragma unroll
        for (int i = 0; i < 16; i++){ accA[i] = 0; accB[i] = 0; }

        // rounds: r0 [x0,x1](s0,s1)  r1 [h0,h1](s2,s3)  r2 [h2,h3](s4,s5)
        //         r3 [h4,h5](s0,s1)  r4 [h6,h7](s2,s3)  r5 [x2,x3](s4,s5)
        // each round: wait; sync; issue-future; compute

        // r0: wait for next-x group (issued last step / primed)
        asm volatile("cp.async.wait_group 0;");
        __syncthreads();
        issue_pair(hrd,          hrd + 4096,   2, 3);   // h0,h1
        issue_pair(hrd + 2*4096, hrd + 3*4096, 4, 5);   // h2,h3
        gemm_slice(stage + 0*4096 + w*512, wib + 0*128, WID_STR, c0, accB);
        gemm_slice(stage + 1*4096 + w*512, wib + 1*128, WID_STR, c0, accB);

        // r1
        asm volatile("cp.async.wait_group 1;");
        __syncthreads();
        issue_pair(hrd + 4*4096, hrd + 5*4096, 0, 1);   // h4,h5 (s0,s1 freed by r0)
        gemm_slice(stage + 2*4096 + w*512, whb + 0*128, WHD_STR, c0, accA);
        gemm_slice(stage + 3*4096 + w*512, whb + 1*128, WHD_STR, c0, accA);

        // r2
        asm volatile("cp.async.wait_group 1;");
        __syncthreads();
        issue_pair(hrd + 6*4096, hrd + 7*4096, 2, 3);   // h6,h7 (s2,s3 freed by r1)
        gemm_slice(stage + 4*4096 + w*512, whb + 2*128, WHD_STR, c0, accA);
        gemm_slice(stage + 5*4096 + w*512, whb + 3*128, WHD_STR, c0, accA);

        // r3
        asm volatile("cp.async.wait_group 1;");
        __syncthreads();
        issue_pair(xt + 2*4096, xt + 3*4096, 4, 5);     // x2,x3 (s4,s5 freed by r2)
        gemm_slice(stage + 0*4096 + w*512, whb + 4*128, WHD_STR, c0, accA);
        gemm_slice(stage + 1*4096 + w*512, whb + 5*128, WHD_STR, c0, accA);

        // r4
        asm volatile("cp.async.wait_group 1;");
        __syncthreads();
        issue_pair(xnx, xnx + 4096, 0, 1);              // next step x0,x1 (s0,s1 freed by r3)
        gemm_slice(stage + 2*4096 + w*512, whb + 6*128, WHD_STR, c0, accA);
        gemm_slice(stage + 3*4096 + w*512, whb + 7*128, WHD_STR, c0, accA);

        // r5 (leave next-x group pending across the tail)
        asm volatile("cp.async.wait_group 1;");
        __syncthreads();
        gemm_slice(stage + 4*4096 + w*512, wib + 2*128, WID_STR, c0, accB);
        gemm_slice(stage + 5*4096 + w*512, wib + 3*128, WID_STR, c0, accB);

        __syncthreads();   // all slot reads done; slots 2..4 become the partial buffer
                           // (disjoint from in-flight next-x in slots 0,1)
        float* pbuf = stage + 2*4096;   // 8704 floats used
        const int rr = tid >> 4, c4 = (tid & 15) * 4;
        float vA[4], vB[4];

        // ---- pass A: hh partials
        {
            float* pp = pbuf + w*(16*PSTR);
            #pragma unroll
            for (int j = 0; j < 4; j++){
                int r2 = rowg + j*4;
                *(ulonglong2*)(pp + r2*PSTR + c0)      = make_ulonglong2(accA[j*4+0], accA[j*4+1]);
                *(ulonglong2*)(pp + r2*PSTR + c0 + 32) = make_ulonglong2(accA[j*4+2], accA[j*4+3]);
            }
        }
        __syncthreads();
        {
            ulonglong2 s = *(const ulonglong2*)(pbuf + rr*PSTR + c4);
            ull ax = s.x, ay = s.y;
            #pragma unroll
            for (int ww = 1; ww < 8; ww++){
                ulonglong2 q = *(const ulonglong2*)(pbuf + ww*(16*PSTR) + rr*PSTR + c4);
                addf2(ax, q.x); addf2(ay, q.y);
            }
            unpack2(ax, vA[0], vA[1]); unpack2(ay, vA[2], vA[3]);
        }
        __syncthreads();

        // ---- pass B: ih partials
        {
            float* pp = pbuf + w*(16*PSTR);
            #pragma unroll
            for (int j = 0; j < 4; j++){
                int r2 = rowg + j*4;
                *(ulonglong2*)(pp + r2*PSTR + c0)      = make_ulonglong2(accB[j*4+0], accB[j*4+1]);
                *(ulonglong2*)(pp + r2*PSTR + c0 + 32) = make_ulonglong2(accB[j*4+2], accB[j*4+3]);
            }
        }
        __syncthreads();
        {
            ulonglong2 s = *(const ulonglong2*)(pbuf + rr*PSTR + c4);
            ull bx = s.x, by = s.y;
            #pragma unroll
            for (int ww = 1; ww < 8; ww++){
                ulonglong2 q = *(const ulonglong2*)(pbuf + ww*(16*PSTR) + rr*PSTR + c4);
                addf2(bx, q.x); addf2(by, q.y);
            }
            unpack2(bx, vB[0], vB[1]); unpack2(by, vB[2], vB[3]);
        }

        // ---- per-gate-row batchnorm
        {
            float sA = vA[0]+vA[1]+vA[2]+vA[3];
            float qA = vA[0]*vA[0]+vA[1]*vA[1]+vA[2]*vA[2]+vA[3]*vA[3];
            float sB = vB[0]+vB[1]+vB[2]+vB[3];
            float qB = vB[0]*vB[0]+vB[1]*vB[1]+vB[2]*vB[2]+vB[3]*vB[3];
            #pragma unroll
            for (int off = 1; off < 16; off <<= 1){
                sA += __shfl_xor_sync(0xffffffffu, sA, off);
                qA += __shfl_xor_sync(0xffffffffu, qA, off);
                sB += __shfl_xor_sync(0xffffffffu, sB, off);
                qB += __shfl_xor_sync(0xffffffffu, qB, off);
            }
            float muA = sA*inv64, muB = sB*inv64;
            float rsA = rsqrtf(qA*inv64 - muA*muA + EPSBN);
            float rsB = rsqrtf(qB*inv64 - muB*muB + EPSBN);
            float ga = ghh_s[rr]*rsA, gb = gih_s[rr]*rsB;
            float cadd = bhh_s[rr] + bih_s[rr] + bias_s[rr] - muA*ga - muB*gb;
            #pragma unroll
            for (int j = 0; j < 4; j++)
                sg[rr*64 + c4 + j] = fmaf(vA[j], ga, fmaf(vB[j], gb, cadd));
        }
        __syncthreads();

        // ---- phase B: gates + cell + c-BN + h (warps 0-3)
        if (w < 4){
            float iv0 = sg[( 0 + w)*64 + lane], iv1 = sg[( 0 + w)*64 + lane + 32];
            float fv0 = sg[( 4 + w)*64 + lane], fv1 = sg[( 4 + w)*64 + lane + 32];
            float gv0 = sg[( 8 + w)*64 + lane], gv1 = sg[( 8 + w)*64 + lane + 32];
            float ov0 = sg[(12 + w)*64 + lane], ov1 = sg[(12 + w)*64 + lane + 32];

            creg0 = sigm(fv0)*creg0 + sigm(iv0)*tanhf(gv0);
            creg1 = sigm(fv1)*creg1 + sigm(iv1)*tanhf(gv1);

            float sc = creg0 + creg1;
            float qc = creg0*creg0 + creg1*creg1;
            #pragma unroll
            for (int off = 16; off >= 1; off >>= 1){
                sc += __shfl_xor_sync(0xffffffffu, sc, off);
                qc += __shfl_xor_sync(0xffffffffu, qc, off);
            }
            float mu = sc*inv64;
            float rs = rsqrtf(qc*inv64 - mu*mu + EPSBN);
            float gcv = gc_s[w]*rs;
            float bcv = bc_s[w] - mu*gcv;
            float h0v = sigm(ov0) * tanhf(fmaf(creg0, gcv, bcv));
            float h1v = sigm(ov1) * tanhf(fmaf(creg1, gcv, bcv));

            int rowg2 = blk*4 + w;
            hwr[rowg2*64 + lane]      = h0v;
            hwr[rowg2*64 + lane + 32] = h1v;
            float* op = out + (size_t)t * (HSZ*BSZ) + rowg2*64;
            op[lane]      = h0v;
            op[lane + 32] = h1v;
        }

        gridsync();
    }
}

extern "C" void kernel_launch(void* const* d_in, const int* in_sizes, int n_in,
                              void* d_out, int out_size)
{
    const float* x    = (const float*)d_in[0];
    const float* Wih  = (const float*)d_in[1];
    const float* Whh  = (const float*)d_in[2];
    const float* bias = (const float*)d_in[3];
    const float* gIH  = (const float*)d_in[4];
    const float* bIH  = (const float*)d_in[5];
    const float* gHH  = (const float*)d_in[6];
    const float* bHH  = (const float*)d_in[7];
    const float* gC   = (const float*)d_in[8];
    const float* bC   = (const float*)d_in[9];
    float* out = (float*)d_out;

    int T = in_sizes[0] / (ISZ * BSZ);   // 2048

    cudaFuncSetAttribute(lstm_bn_kernel,
                         cudaFuncAttributeMaxDynamicSharedMemorySize, SMEM_BYTES);
    lstm_bn_kernel<<<NBLK, NTHR, SMEM_BYTES>>>(x, Wih, Whh, bias,
                                               gIH, bIH, gHH, bHH, gC, bC,
                                               out, T);
}

// round 14
// speedup vs baseline: 1.4903x; 1.4593x over previous
#include <cuda_runtime.h>
#include <cstdint>

#define HSZ   512
#define ISZ   256
#define BSZ   64
#define NBLK  128
#define NTHR  256
#define WCB_STR 1540   // 512 (ih dup) + 1024 (hh dup) + 4 pad  (≡4 mod 32)
#define PSTR    68
#define EPSBN 1e-5f

// smem layout (floats)
#define OFF_WCB  0                              // 16 rows x 1540
#define OFF_ST   (OFF_WCB + 16*WCB_STR)         // 24640 (6 slots x 4096 = 96KB; slots 2..4 reused for partials)
#define OFF_SG   (OFF_ST + 6*4096)              // 49216
#define OFF_CST  (OFF_SG + 16*64)               // 50240
#define SMEM_FLOATS (OFF_CST + 96)              // 50336
#define SMEM_BYTES  (SMEM_FLOATS*4)             // 201344 B ≈ 196.6 KB

#define SLOT_BYTES 16384u

__device__ float g_h[2][HSZ*BSZ];
__device__ unsigned g_arrive;
__device__ unsigned g_release;

typedef unsigned long long ull;

__device__ __forceinline__ void unpack2(ull v, float &lo, float &hi){
    asm("mov.b64 {%0, %1}, %2;" : "=f"(lo), "=f"(hi) : "l"(v));
}
__device__ __forceinline__ void ffma2(ull &acc, ull a, ull b){
    asm("fma.rn.f32x2 %0, %1, %2, %0;" : "+l"(acc) : "l"(a), "l"(b));
}
__device__ __forceinline__ void addf2(ull &acc, ull a){
    asm("add.rn.f32x2 %0, %0, %1;" : "+l"(acc) : "l"(a));
}
__device__ __forceinline__ void cp16(uint32_t dst, const void* src){
    asm volatile("cp.async.cg.shared.global [%0], [%1], 16;" :: "r"(dst), "l"(src));
}
__device__ __forceinline__ float sigm(float x){
    return 1.0f / (1.0f + __expf(-x));
}
__device__ __forceinline__ int slot6(int v){ return v % 6; }

// 8-k slice of one chunk: 4 rows x 8 cols (16 f32x2 acc). Row stride = 4*WCB_STR (compile-time).
__device__ __forceinline__ void gemm_slice(const float* __restrict__ st,
                                           const float* __restrict__ wb,
                                           int c0, ull* __restrict__ acc)
{
    #pragma unroll
    for (int g = 0; g < 2; g++){
        ulonglong2 w0l = *(const ulonglong2*)(wb + 0*4*WCB_STR + g*8);
        ulonglong2 w0h = *(const ulonglong2*)(wb + 0*4*WCB_STR + g*8 + 4);
        ulonglong2 w1l = *(const ulonglong2*)(wb + 1*4*WCB_STR + g*8);
        ulonglong2 w1h = *(const ulonglong2*)(wb + 1*4*WCB_STR + g*8 + 4);
        ulonglong2 w2l = *(const ulonglong2*)(wb + 2*4*WCB_STR + g*8);
        ulonglong2 w2h = *(const ulonglong2*)(wb + 2*4*WCB_STR + g*8 + 4);
        ulonglong2 w3l = *(const ulonglong2*)(wb + 3*4*WCB_STR + g*8);
        ulonglong2 w3h = *(const ulonglong2*)(wb + 3*4*WCB_STR + g*8 + 4);
        #pragma unroll
        for (int kk = 0; kk < 4; kk++){
            const float* sp = st + (g*4 + kk)*64 + c0;
            ulonglong2 sa = *(const ulonglong2*)(sp);
            ulonglong2 sb = *(const ulonglong2*)(sp + 32);
            ull w0 = (kk==0)?w0l.x:(kk==1)?w0l.y:(kk==2)?w0h.x:w0h.y;
            ull w1 = (kk==0)?w1l.x:(kk==1)?w1l.y:(kk==2)?w1h.x:w1h.y;
            ull w2 = (kk==0)?w2l.x:(kk==1)?w2l.y:(kk==2)?w2h.x:w2h.y;
            ull w3 = (kk==0)?w3l.x:(kk==1)?w3l.y:(kk==2)?w3h.x:w3h.y;
            ffma2(acc[ 0], w0, sa.x); ffma2(acc[ 1], w0, sa.y);
            ffma2(acc[ 2], w0, sb.x); ffma2(acc[ 3], w0, sb.y);
            ffma2(acc[ 4], w1, sa.x); ffma2(acc[ 5], w1, sa.y);
            ffma2(acc[ 6], w1, sb.x); ffma2(acc[ 7], w1, sb.y);
            ffma2(acc[ 8], w2, sa.x); ffma2(acc[ 9], w2, sa.y);
            ffma2(acc[10], w2, sb.x); ffma2(acc[11], w2, sb.y);
            ffma2(acc[12], w3, sa.x); ffma2(acc[13], w3, sa.y);
            ffma2(acc[14], w3, sb.x); ffma2(acc[15], w3, sb.y);
        }
    }
}

extern "C" __global__ void __launch_bounds__(NTHR, 1)
lstm_bn_kernel(const float* __restrict__ x,
               const float* __restrict__ Wih,
               const float* __restrict__ Whh,
               const float* __restrict__ bias,
               const float* __restrict__ gIH, const float* __restrict__ bIH,
               const float* __restrict__ gHH, const float* __restrict__ bHH,
               const float* __restrict__ gC,  const float* __restrict__ bC,
               float* __restrict__ out, int T)
{
    extern __shared__ float sm[];
    float* wcb    = sm + OFF_WCB;
    float* stage  = sm + OFF_ST;
    float* sg     = sm + OFF_SG;
    float* ghh_s  = sm + OFF_CST;
    float* bhh_s  = ghh_s + 16;
    float* gih_s  = bhh_s + 16;
    float* bih_s  = gih_s + 16;
    float* bias_s = bih_s + 16;
    float* gc_s   = bias_s + 16;
    float* bc_s   = gc_s + 4;

    const int tid  = threadIdx.x;
    const int blk  = blockIdx.x;
    const int w    = tid >> 5;
    const int lane = tid & 31;
    const int rowg = lane >> 3;
    const int colg = lane & 7;
    const int c0   = colg * 4;

    // ---- preload combined weights, DUPLICATED: row = [ih 512 dup][hh 1024 dup][pad]
    for (int idx = tid; idx < 16*ISZ; idx += NTHR){
        int l = idx >> 8, k = idx & 255;
        int grow = (l >> 2) * HSZ + blk*4 + (l & 3);
        float v = Wih[(size_t)grow * ISZ + k];
        wcb[l*WCB_STR + 2*k]     = v;
        wcb[l*WCB_STR + 2*k + 1] = v;
    }
    for (int idx = tid; idx < 16*HSZ; idx += NTHR){
        int l = idx >> 9, k = idx & 511;
        int grow = (l >> 2) * HSZ + blk*4 + (l & 3);
        float v = Whh[(size_t)grow * HSZ + k];
        wcb[l*WCB_STR + 512 + 2*k]     = v;
        wcb[l*WCB_STR + 512 + 2*k + 1] = v;
    }
    if (tid < 16){
        int grow = (tid >> 2) * HSZ + blk*4 + (tid & 3);
        ghh_s[tid] = gHH[grow]; bhh_s[tid] = bHH[grow];
        gih_s[tid] = gIH[grow]; bih_s[tid] = bIH[grow];
        bias_s[tid] = bias[grow];
    }
    if (tid < 4){ gc_s[tid] = gC[blk*4 + tid]; bc_s[tid] = bC[blk*4 + tid]; }

    g_h[0][blk * NTHR + tid] = 0.f;
    __syncthreads();

    unsigned gen0 = 0, my_gen = 0;
    if (tid == 0) gen0 = *((volatile unsigned*)&g_release);

    auto gridsync = [&](){
        __syncthreads();
        if (tid == 0){
            my_gen++;
            __threadfence();
            unsigned a = atomicAdd(&g_arrive, 1u);
            if (a == (unsigned)(NBLK - 1)){
                atomicExch(&g_arrive, 0u);
                __threadfence();
                atomicAdd(&g_release, 1u);
            } else {
                while ( (*((volatile unsigned*)&g_release)) - gen0 < my_gen ) { }
            }
        }
        __syncthreads();
    };

    const uint32_t stBase = (uint32_t)__cvta_generic_to_shared(stage);
    const float inv64 = 1.0f / 64.0f;
    float creg0 = 0.f, creg1 = 0.f;

    const float* wcbt = wcb + rowg*WCB_STR + w*16;   // thread weight base; + chunk*128

    auto issue_pair = [&](const float* cA, const float* cB, int sa, int sb){
        uint32_t dA = stBase + (uint32_t)sa * SLOT_BYTES;
        uint32_t dB = stBase + (uint32_t)sb * SLOT_BYTES;
        #pragma unroll
        for (int j = 0; j < 4; j++){
            cp16(dA + (uint32_t)(tid + j*256)*16u, cA + (tid + j*256)*4);
            cp16(dB + (uint32_t)(tid + j*256)*16u, cB + (tid + j*256)*4);
        }
        asm volatile("cp.async.commit_group;");
    };

    // ---- prime: step-0 x pairs P0 (slots 0,1) and P1 (slots 2,3)
    issue_pair(x,          x + 4096,   0, 1);
    issue_pair(x + 2*4096, x + 3*4096, 2, 3);

    gridsync();   // h zeroed everywhere before step 0

    for (int t = 0; t < T; t++){
        const float* hrd = g_h[t & 1];
        float*       hwr = g_h[(t + 1) & 1];
        const float* xnx = x + (size_t)((t+1 < T) ? (t+1) : (T-1)) * (ISZ*BSZ);

        ull accA[16], accB[16];
        #pragma unroll
        for (int i = 0; i < 16; i++){ accA[i] = 0; accB[i] = 0; }

        // pairs: p=0 [x0,x1] p=1 [x2,x3] p=2 [h0,h1] p=3 [h2,h3] p=4 [h4,h5] p=5 [h6,h7]
        // round r: wait oldest-but-one; sync; issue pair r+2 (r=4 -> next-x P0); compute pair r.
        // slots(p) = (2p)%6,(2p+1)%6. Weight offset of chunk cc = cc*128 (uniform by layout).

        #pragma unroll 1
        for (int r = 0; r < 2; r++){              // x pairs -> accB
            asm volatile("cp.async.wait_group 1;");
            __syncthreads();
            issue_pair(hrd + 2*r*4096, hrd + (2*r+1)*4096, slot6(2*r+4), slot6(2*r+5));
            gemm_slice(stage + slot6(2*r  )*4096 + w*512, wcbt + (2*r  )*128, c0, accB);
            gemm_slice(stage + slot6(2*r+1)*4096 + w*512, wcbt + (2*r+1)*128, c0, accB);
        }
        #pragma unroll 1
        for (int r = 2; r < 6; r++){              // h pairs -> accA
            asm volatile("cp.async.wait_group 1;");
            __syncthreads();
            if (r < 4)
                issue_pair(hrd + 2*r*4096, hrd + (2*r+1)*4096, slot6(2*r+4), slot6(2*r+5));
            else if (r == 4)
                issue_pair(xnx, xnx + 4096, 0, 1);     // next-x P0
            gemm_slice(stage + slot6(2*r  )*4096 + w*512, wcbt + (2*r  )*128, c0, accA);
            gemm_slice(stage + slot6(2*r+1)*4096 + w*512, wcbt + (2*r+1)*128, c0, accA);
        }

        __syncthreads();   // all slot reads done; slots 2..4 = partial buffer (nx0 in slots 0,1)
        float* pbuf = stage + 2*4096;
        const int rr = tid >> 4, c4 = (tid & 15) * 4;
        float vA[4], vB[4];

        // ---- pass A: hh partials
        {
            float* pp = pbuf + w*(16*PSTR);
            #pragma unroll
            for (int j = 0; j < 4; j++){
                int r2 = rowg + j*4;
                *(ulonglong2*)(pp + r2*PSTR + c0)      = make_ulonglong2(accA[j*4+0], accA[j*4+1]);
                *(ulonglong2*)(pp + r2*PSTR + c0 + 32) = make_ulonglong2(accA[j*4+2], accA[j*4+3]);
            }
        }
        __syncthreads();
        {
            ulonglong2 s = *(const ulonglong2*)(pbuf + rr*PSTR + c4);
            ull ax = s.x, ay = s.y;
            #pragma unroll
            for (int ww = 1; ww < 8; ww++){
                ulonglong2 q = *(const ulonglong2*)(pbuf + ww*(16*PSTR) + rr*PSTR + c4);
                addf2(ax, q.x); addf2(ay, q.y);
            }
            unpack2(ax, vA[0], vA[1]); unpack2(ay, vA[2], vA[3]);
        }
        __syncthreads();

        // ---- pass B: ih partials
        {
            float* pp = pbuf + w*(16*PSTR);
            #pragma unroll
            for (int j = 0; j < 4; j++){
                int r2 = rowg + j*4;
                *(ulonglong2*)(pp + r2*PSTR + c0)      = make_ulonglong2(accB[j*4+0], accB[j*4+1]);
                *(ulonglong2*)(pp + r2*PSTR + c0 + 32) = make_ulonglong2(accB[j*4+2], accB[j*4+3]);
            }
        }
        __syncthreads();
        {
            ulonglong2 s = *(const ulonglong2*)(pbuf + rr*PSTR + c4);
            ull bx = s.x, by = s.y;
            #pragma unroll
            for (int ww = 1; ww < 8; ww++){
                ulonglong2 q = *(const ulonglong2*)(pbuf + ww*(16*PSTR) + rr*PSTR + c4);
                addf2(bx, q.x); addf2(by, q.y);
            }
            unpack2(bx, vB[0], vB[1]); unpack2(by, vB[2], vB[3]);
        }

        // ---- per-gate-row batchnorm
        {
            float sA = vA[0]+vA[1]+vA[2]+vA[3];
            float qA = vA[0]*vA[0]+vA[1]*vA[1]+vA[2]*vA[2]+vA[3]*vA[3];
            float sB = vB[0]+vB[1]+vB[2]+vB[3];
            float qB = vB[0]*vB[0]+vB[1]*vB[1]+vB[2]*vB[2]+vB[3]*vB[3];
            #pragma unroll
            for (int off = 1; off < 16; off <<= 1){
                sA += __shfl_xor_sync(0xffffffffu, sA, off);
                qA += __shfl_xor_sync(0xffffffffu, qA, off);
                sB += __shfl_xor_sync(0xffffffffu, sB, off);
                qB += __shfl_xor_sync(0xffffffffu, qB, off);
            }
            float muA = sA*inv64, muB = sB*inv64;
            float rsA = rsqrtf(qA*inv64 - muA*muA + EPSBN);
            float rsB = rsqrtf(qB*inv64 - muB*muB + EPSBN);
            float ga = ghh_s[rr]*rsA, gb = gih_s[rr]*rsB;
            float cadd = bhh_s[rr] + bih_s[rr] + bias_s[rr] - muA*ga - muB*gb;
            #pragma unroll
            for (int j = 0; j < 4; j++)
                sg[rr*64 + c4 + j] = fmaf(vA[j], ga, fmaf(vB[j], gb, cadd));
        }
        __syncthreads();   // pbuf reads done; sg published

        // issue next-x P1 (slots 2,3) — overlaps phase B + gridsync
        issue_pair(xnx + 2*4096, xnx + 3*4096, 2, 3);

        // ---- phase B: gates + cell + c-BN + h (warps 0-3)
        if (w < 4){
            float iv0 = sg[( 0 + w)*64 + lane], iv1 = sg[( 0 + w)*64 + lane + 32];
            float fv0 = sg[( 4 + w)*64 + lane], fv1 = sg[( 4 + w)*64 + lane + 32];
            float gv0 = sg[( 8 + w)*64 + lane], gv1 = sg[( 8 + w)*64 + lane + 32];
            float ov0 = sg[(12 + w)*64 + lane], ov1 = sg[(12 + w)*64 + lane + 32];

            creg0 = sigm(fv0)*creg0 + sigm(iv0)*tanhf(gv0);
            creg1 = sigm(fv1)*creg1 + sigm(iv1)*tanhf(gv1);

            float sc = creg0 + creg1;
            float qc = creg0*creg0 + creg1*creg1;
            #pragma unroll
            for (int off = 16; off >= 1; off >>= 1){
                sc += __shfl_xor_sync(0xffffffffu, sc, off);
                qc += __shfl_xor_sync(0xffffffffu, qc, off);
            }
            float mu = sc*inv64;
            float rs = rsqrtf(qc*inv64 - mu*mu + EPSBN);
            float gcv = gc_s[w]*rs;
            float bcv = bc_s[w] - mu*gcv;
            float h0v = sigm(ov0) * tanhf(fmaf(creg0, gcv, bcv));
            float h1v = sigm(ov1) * tanhf(fmaf(creg1, gcv, bcv));

            int rowg2 = blk*4 + w;
            hwr[rowg2*64 + lane]      = h0v;
            hwr[rowg2*64 + lane + 32] = h1v;
            float* op = out + (size_t)t * (HSZ*BSZ) + rowg2*64;
            op[lane]      = h0v;
            op[lane + 32] = h1v;
        }

        gridsync();
    }
}

extern "C" void kernel_launch(void* const* d_in, const int* in_sizes, int n_in,
                              void* d_out, int out_size)
{
    const float* x    = (const float*)d_in[0];
    const float* Wih  = (const float*)d_in[1];
    const float* Whh  = (const float*)d_in[2];
    const float* bias = (const float*)d_in[3];
    const float* gIH  = (const float*)d_in[4];
    const float* bIH  = (const float*)d_in[5];
    const float* gHH  = (const float*)d_in[6];
    const float* bHH  = (const float*)d_in[7];
    const float* gC   = (const float*)d_in[8];
    const float* bC   = (const float*)d_in[9];
    float* out = (float*)d_out;

    int T = in_sizes[0] / (ISZ * BSZ);   // 2048

    cudaFuncSetAttribute(lstm_bn_kernel,
                         cudaFuncAttributeMaxDynamicSharedMemorySize, SMEM_BYTES);
    lstm_bn_kernel<<<NBLK, NTHR, SMEM_BYTES>>>(x, Wih, Whh, bias,
                                               gIH, bIH, gHH, bHH, gC, bC,
                                               out, T);
}

// round 15
// speedup vs baseline: 1.5531x; 1.0422x over previous
#include <cuda_runtime.h>
#include <cstdint>

#define HSZ   512
#define ISZ   256
#define BSZ   64
#define NBLK  128
#define NTHR  256
#define WCB_STR 1540   // 512 (ih dup) + 1024 (hh dup) + 4 pad  (≡4 mod 32)
#define PSTR    68
#define EPSBN 1e-5f

// smem layout (floats)
#define OFF_WCB  0                              // 16 rows x 1540
#define OFF_ST   (OFF_WCB + 16*WCB_STR)         // 24640 (6 slots x 4096 = 96KB; fully reused for partials in tail)
#define OFF_SG   (OFF_ST + 6*4096)              // 49216
#define OFF_CST  (OFF_SG + 16*64)               // 50240
#define SMEM_FLOATS (OFF_CST + 96)              // 50336
#define SMEM_BYTES  (SMEM_FLOATS*4)             // ~196.6 KB

#define SLOT_BYTES 16384u

__device__ float g_h[2][HSZ*BSZ];
__device__ unsigned g_arrive;
__device__ unsigned g_release;

typedef unsigned long long ull;

__device__ __forceinline__ void unpack2(ull v, float &lo, float &hi){
    asm("mov.b64 {%0, %1}, %2;" : "=f"(lo), "=f"(hi) : "l"(v));
}
__device__ __forceinline__ void ffma2(ull &acc, ull a, ull b){
    asm("fma.rn.f32x2 %0, %1, %2, %0;" : "+l"(acc) : "l"(a), "l"(b));
}
__device__ __forceinline__ void addf2(ull &acc, ull a){
    asm("add.rn.f32x2 %0, %0, %1;" : "+l"(acc) : "l"(a));
}
__device__ __forceinline__ void cp16(uint32_t dst, const void* src){
    asm volatile("cp.async.cg.shared.global [%0], [%1], 16;" :: "r"(dst), "l"(src));
}
__device__ __forceinline__ float sigm(float x){
    return __fdividef(1.0f, 1.0f + __expf(-x));
}
__device__ __forceinline__ float ftanh(float x){
    float e = __expf(2.0f * x);
    return 1.0f - __fdividef(2.0f, e + 1.0f);
}
__device__ __forceinline__ int slot6(int v){ return v % 6; }

// 8-k slice of one chunk: 4 rows x 8 cols (16 f32x2 acc). Row stride = 4*WCB_STR (compile-time).
__device__ __forceinline__ void gemm_slice(const float* __restrict__ st,
                                           const float* __restrict__ wb,
                                           int c0, ull* __restrict__ acc)
{
    #pragma unroll
    for (int g = 0; g < 2; g++){
        ulonglong2 w0l = *(const ulonglong2*)(wb + 0*4*WCB_STR + g*8);
        ulonglong2 w0h = *(const ulonglong2*)(wb + 0*4*WCB_STR + g*8 + 4);
        ulonglong2 w1l = *(const ulonglong2*)(wb + 1*4*WCB_STR + g*8);
        ulonglong2 w1h = *(const ulonglong2*)(wb + 1*4*WCB_STR + g*8 + 4);
        ulonglong2 w2l = *(const ulonglong2*)(wb + 2*4*WCB_STR + g*8);
        ulonglong2 w2h = *(const ulonglong2*)(wb + 2*4*WCB_STR + g*8 + 4);
        ulonglong2 w3l = *(const ulonglong2*)(wb + 3*4*WCB_STR + g*8);
        ulonglong2 w3h = *(const ulonglong2*)(wb + 3*4*WCB_STR + g*8 + 4);
        #pragma unroll
        for (int kk = 0; kk < 4; kk++){
            const float* sp = st + (g*4 + kk)*64 + c0;
            ulonglong2 sa = *(const ulonglong2*)(sp);
            ulonglong2 sb = *(const ulonglong2*)(sp + 32);
            ull w0 = (kk==0)?w0l.x:(kk==1)?w0l.y:(kk==2)?w0h.x:w0h.y;
            ull w1 = (kk==0)?w1l.x:(kk==1)?w1l.y:(kk==2)?w1h.x:w1h.y;
            ull w2 = (kk==0)?w2l.x:(kk==1)?w2l.y:(kk==2)?w2h.x:w2h.y;
            ull w3 = (kk==0)?w3l.x:(kk==1)?w3l.y:(kk==2)?w3h.x:w3h.y;
            ffma2(acc[ 0], w0, sa.x); ffma2(acc[ 1], w0, sa.y);
            ffma2(acc[ 2], w0, sb.x); ffma2(acc[ 3], w0, sb.y);
            ffma2(acc[ 4], w1, sa.x); ffma2(acc[ 5], w1, sa.y);
            ffma2(acc[ 6], w1, sb.x); ffma2(acc[ 7], w1, sb.y);
            ffma2(acc[ 8], w2, sa.x); ffma2(acc[ 9], w2, sa.y);
            ffma2(acc[10], w2, sb.x); ffma2(acc[11], w2, sb.y);
            ffma2(acc[12], w3, sa.x); ffma2(acc[13], w3, sa.y);
            ffma2(acc[14], w3, sb.x); ffma2(acc[15], w3, sb.y);
        }
    }
}

extern "C" __global__ void __launch_bounds__(NTHR, 1)
lstm_bn_kernel(const float* __restrict__ x,
               const float* __restrict__ Wih,
               const float* __restrict__ Whh,
               const float* __restrict__ bias,
               const float* __restrict__ gIH, const float* __restrict__ bIH,
               const float* __restrict__ gHH, const float* __restrict__ bHH,
               const float* __restrict__ gC,  const float* __restrict__ bC,
               float* __restrict__ out, int T)
{
    extern __shared__ float sm[];
    float* wcb    = sm + OFF_WCB;
    float* stage  = sm + OFF_ST;
    float* sg     = sm + OFF_SG;
    float* ghh_s  = sm + OFF_CST;
    float* bhh_s  = ghh_s + 16;
    float* gih_s  = bhh_s + 16;
    float* bih_s  = gih_s + 16;
    float* bias_s = bih_s + 16;
    float* gc_s   = bias_s + 16;
    float* bc_s   = gc_s + 4;

    const int tid  = threadIdx.x;
    const int blk  = blockIdx.x;
    const int w    = tid >> 5;
    const int lane = tid & 31;
    const int rowg = lane >> 3;
    const int colg = lane & 7;
    const int c0   = colg * 4;

    // ---- preload combined weights, DUPLICATED: row = [ih 512 dup][hh 1024 dup][pad]
    for (int idx = tid; idx < 16*ISZ; idx += NTHR){
        int l = idx >> 8, k = idx & 255;
        int grow = (l >> 2) * HSZ + blk*4 + (l & 3);
        float v = Wih[(size_t)grow * ISZ + k];
        wcb[l*WCB_STR + 2*k]     = v;
        wcb[l*WCB_STR + 2*k + 1] = v;
    }
    for (int idx = tid; idx < 16*HSZ; idx += NTHR){
        int l = idx >> 9, k = idx & 511;
        int grow = (l >> 2) * HSZ + blk*4 + (l & 3);
        float v = Whh[(size_t)grow * HSZ + k];
        wcb[l*WCB_STR + 512 + 2*k]     = v;
        wcb[l*WCB_STR + 512 + 2*k + 1] = v;
    }
    if (tid < 16){
        int grow = (tid >> 2) * HSZ + blk*4 + (tid & 3);
        ghh_s[tid] = gHH[grow]; bhh_s[tid] = bHH[grow];
        gih_s[tid] = gIH[grow]; bih_s[tid] = bIH[grow];
        bias_s[tid] = bias[grow];
    }
    if (tid < 4){ gc_s[tid] = gC[blk*4 + tid]; bc_s[tid] = bC[blk*4 + tid]; }

    g_h[0][blk * NTHR + tid] = 0.f;
    __syncthreads();

    unsigned gen0 = 0, my_gen = 0;
    if (tid == 0) gen0 = *((volatile unsigned*)&g_release);

    auto gridsync = [&](){
        __syncthreads();
        if (tid == 0){
            my_gen++;
            __threadfence();
            unsigned a = atomicAdd(&g_arrive, 1u);
            if (a == (unsigned)(NBLK - 1)){
                atomicExch(&g_arrive, 0u);
                __threadfence();
                atomicAdd(&g_release, 1u);
            } else {
                while ( (*((volatile unsigned*)&g_release)) - gen0 < my_gen ) { }
            }
        }
        __syncthreads();
    };

    const uint32_t stBase = (uint32_t)__cvta_generic_to_shared(stage);
    const float inv64 = 1.0f / 64.0f;
    float creg0 = 0.f, creg1 = 0.f;

    const float* wcbt = wcb + rowg*WCB_STR + w*16;   // thread weight base; + chunk*128

    auto issue_pair = [&](const float* cA, const float* cB, int sa, int sb){
        uint32_t dA = stBase + (uint32_t)sa * SLOT_BYTES;
        uint32_t dB = stBase + (uint32_t)sb * SLOT_BYTES;
        #pragma unroll
        for (int j = 0; j < 4; j++){
            cp16(dA + (uint32_t)(tid + j*256)*16u, cA + (tid + j*256)*4);
            cp16(dB + (uint32_t)(tid + j*256)*16u, cB + (tid + j*256)*4);
        }
        asm volatile("cp.async.commit_group;");
    };

    // ---- prime: step-0 x pairs P0 (slots 0,1) and P1 (slots 2,3)
    issue_pair(x,          x + 4096,   0, 1);
    issue_pair(x + 2*4096, x + 3*4096, 2, 3);

    gridsync();   // h zeroed everywhere before step 0

    for (int t = 0; t < T; t++){
        const float* hrd = g_h[t & 1];
        float*       hwr = g_h[(t + 1) & 1];
        const float* xnx = x + (size_t)((t+1 < T) ? (t+1) : (T-1)) * (ISZ*BSZ);

        ull accA[16], accB[16];
        #pragma unroll
        for (int i = 0; i < 16; i++){ accA[i] = 0; accB[i] = 0; }

        // pairs: p=0 [x0,x1] p=1 [x2,x3] p=2 [h0,h1] p=3 [h2,h3] p=4 [h4,h5] p=5 [h6,h7]
        // slots(p) = (2p)%6,(2p+1)%6. Round r computes pair r; rounds 0..3 issue pair r+2.
        // No group is left pending into the tail (next-x is issued in the tail).

        #pragma unroll 1
        for (int r = 0; r < 2; r++){              // x pairs -> accB
            asm volatile("cp.async.wait_group 1;");
            __syncthreads();
            issue_pair(hrd + 2*r*4096, hrd + (2*r+1)*4096, slot6(2*r+4), slot6(2*r+5));
            gemm_slice(stage + slot6(2*r  )*4096 + w*512, wcbt + (2*r  )*128, c0, accB);
            gemm_slice(stage + slot6(2*r+1)*4096 + w*512, wcbt + (2*r+1)*128, c0, accB);
        }
        #pragma unroll 1
        for (int r = 2; r < 5; r++){              // h pairs -> accA
            asm volatile("cp.async.wait_group 1;");
            __syncthreads();
            if (r < 4)
                issue_pair(hrd + 2*r*4096, hrd + (2*r+1)*4096, slot6(2*r+4), slot6(2*r+5));
            gemm_slice(stage + slot6(2*r  )*4096 + w*512, wcbt + (2*r  )*128, c0, accA);
            gemm_slice(stage + slot6(2*r+1)*4096 + w*512, wcbt + (2*r+1)*128, c0, accA);
        }
        // r5 peeled: nothing else pending -> wait all
        asm volatile("cp.async.wait_group 0;");
        __syncthreads();
        gemm_slice(stage + 4*4096 + w*512, wcbt + 10*128, c0, accA);
        gemm_slice(stage + 5*4096 + w*512, wcbt + 11*128, c0, accA);

        __syncthreads();   // all slot reads done; entire ring becomes the partial buffer
        float* pbufA = stage;                 // 8704 floats
        float* pbufB = stage + 8*16*PSTR;     // 8704 floats (<= 24576 total)
        const int rr = tid >> 4, c4 = (tid & 15) * 4;
        float vA[4], vB[4];

        // ---- single-pass: write hh AND ih partials, one barrier, one reduce
        {
            float* pa = pbufA + w*(16*PSTR);
            float* pb = pbufB + w*(16*PSTR);
            #pragma unroll
            for (int j = 0; j < 4; j++){
                int r2 = rowg + j*4;
                *(ulonglong2*)(pa + r2*PSTR + c0)      = make_ulonglong2(accA[j*4+0], accA[j*4+1]);
                *(ulonglong2*)(pa + r2*PSTR + c0 + 32) = make_ulonglong2(accA[j*4+2], accA[j*4+3]);
                *(ulonglong2*)(pb + r2*PSTR + c0)      = make_ulonglong2(accB[j*4+0], accB[j*4+1]);
                *(ulonglong2*)(pb + r2*PSTR + c0 + 32) = make_ulonglong2(accB[j*4+2], accB[j*4+3]);
            }
        }
        __syncthreads();
        {
            ulonglong2 s = *(const ulonglong2*)(pbufA + rr*PSTR + c4);
            ulonglong2 u = *(const ulonglong2*)(pbufB + rr*PSTR + c4);
            ull ax = s.x, ay = s.y, bx = u.x, by = u.y;
            #pragma unroll
            for (int ww = 1; ww < 8; ww++){
                ulonglong2 qa = *(const ulonglong2*)(pbufA + ww*(16*PSTR) + rr*PSTR + c4);
                ulonglong2 qb = *(const ulonglong2*)(pbufB + ww*(16*PSTR) + rr*PSTR + c4);
                addf2(ax, qa.x); addf2(ay, qa.y);
                addf2(bx, qb.x); addf2(by, qb.y);
            }
            unpack2(ax, vA[0], vA[1]); unpack2(ay, vA[2], vA[3]);
            unpack2(bx, vB[0], vB[1]); unpack2(by, vB[2], vB[3]);
        }
        __syncthreads();   // reduction reads complete -> ring slots reusable

        // issue next-x pairs into slots 0-3 (dead); overlap BN + phase B + gridsync
        issue_pair(xnx,          xnx + 4096,   0, 1);
        issue_pair(xnx + 2*4096, xnx + 3*4096, 2, 3);

        // ---- per-gate-row batchnorm (thread owns row rr, cols c4..c4+3)
        {
            float sA = vA[0]+vA[1]+vA[2]+vA[3];
            float qA = vA[0]*vA[0]+vA[1]*vA[1]+vA[2]*vA[2]+vA[3]*vA[3];
            float sB = vB[0]+vB[1]+vB[2]+vB[3];
            float qB = vB[0]*vB[0]+vB[1]*vB[1]+vB[2]*vB[2]+vB[3]*vB[3];
            #pragma unroll
            for (int off = 1; off < 16; off <<= 1){
                sA += __shfl_xor_sync(0xffffffffu, sA, off);
                qA += __shfl_xor_sync(0xffffffffu, qA, off);
                sB += __shfl_xor_sync(0xffffffffu, sB, off);
                qB += __shfl_xor_sync(0xffffffffu, qB, off);
            }
            float muA = sA*inv64, muB = sB*inv64;
            float rsA = rsqrtf(qA*inv64 - muA*muA + EPSBN);
            float rsB = rsqrtf(qB*inv64 - muB*muB + EPSBN);
            float ga = ghh_s[rr]*rsA, gb = gih_s[rr]*rsB;
            float cadd = bhh_s[rr] + bih_s[rr] + bias_s[rr] - muA*ga - muB*gb;
            #pragma unroll
            for (int j = 0; j < 4; j++)
                sg[rr*64 + c4 + j] = fmaf(vA[j], ga, fmaf(vB[j], gb, cadd));
        }
        __syncthreads();   // sg published

        // ---- phase B: gates + cell + c-BN + h (warps 0-3; warp w owns h-row blk*4+w)
        if (w < 4){
            float iv0 = sg[( 0 + w)*64 + lane], iv1 = sg[( 0 + w)*64 + lane + 32];
            float fv0 = sg[( 4 + w)*64 + lane], fv1 = sg[( 4 + w)*64 + lane + 32];
            float gv0 = sg[( 8 + w)*64 + lane], gv1 = sg[( 8 + w)*64 + lane + 32];
            float ov0 = sg[(12 + w)*64 + lane], ov1 = sg[(12 + w)*64 + lane + 32];

            creg0 = sigm(fv0)*creg0 + sigm(iv0)*ftanh(gv0);
            creg1 = sigm(fv1)*creg1 + sigm(iv1)*ftanh(gv1);

            float sc = creg0 + creg1;
            float qc = creg0*creg0 + creg1*creg1;
            #pragma unroll
            for (int off = 16; off >= 1; off >>= 1){
                sc += __shfl_xor_sync(0xffffffffu, sc, off);
                qc += __shfl_xor_sync(0xffffffffu, qc, off);
            }
            float mu = sc*inv64;
            float rs = rsqrtf(qc*inv64 - mu*mu + EPSBN);
            float gcv = gc_s[w]*rs;
            float bcv = bc_s[w] - mu*gcv;
            float h0v = sigm(ov0) * ftanh(fmaf(creg0, gcv, bcv));
            float h1v = sigm(ov1) * ftanh(fmaf(creg1, gcv, bcv));

            int rowg2 = blk*4 + w;
            hwr[rowg2*64 + lane]      = h0v;
            hwr[rowg2*64 + lane + 32] = h1v;
            float* op = out + (size_t)t * (HSZ*BSZ) + rowg2*64;
            op[lane]      = h0v;
            op[lane + 32] = h1v;
        }

        gridsync();
    }
}

extern "C" void kernel_launch(void* const* d_in, const int* in_sizes, int n_in,
                              void* d_out, int out_size)
{
    const float* x    = (const float*)d_in[0];
    const float* Wih  = (const float*)d_in[1];
    const float* Whh  = (const float*)d_in[2];
    const float* bias = (const float*)d_in[3];
    const float* gIH  = (const float*)d_in[4];
    const float* bIH  = (const float*)d_in[5];
    const float* gHH  = (const float*)d_in[6];
    const float* bHH  = (const float*)d_in[7];
    const float* gC   = (const float*)d_in[8];
    const float* bC   = (const float*)d_in[9];
    float* out = (float*)d_out;

    int T = in_sizes[0] / (ISZ * BSZ);   // 2048

    cudaFuncSetAttribute(lstm_bn_kernel,
                         cudaFuncAttributeMaxDynamicSharedMemorySize, SMEM_BYTES);
    lstm_bn_kernel<<<NBLK, NTHR, SMEM_BYTES>>>(x, Wih, Whh, bias,
                                               gIH, bIH, gHH, bHH, gC, bC,
                                               out, T);
}

// round 16
// speedup vs baseline: 1.6468x; 1.0603x over previous
#include <cuda_runtime.h>
#include <cstdint>

#define HSZ   512
#define ISZ   256
#define BSZ   64
#define NBLK  128
#define NTHR  256
#define WCB_STR 1540   // 512 (ih dup) + 1024 (hh dup) + 4 pad  (≡4 mod 32)
#define PSTR    68
#define EPSBN 1e-5f

// smem layout (floats)
#define OFF_WCB  0                              // 16 rows x 1540
#define OFF_ST   (OFF_WCB + 16*WCB_STR)         // 6 slots x 4096 = 96KB; reused for partials in tail
#define OFF_SG   (OFF_ST + 6*4096)
#define OFF_CST  (OFF_SG + 16*64)
#define SMEM_FLOATS (OFF_CST + 96)
#define SMEM_BYTES  (SMEM_FLOATS*4)             // ~196.6 KB

#define SLOT_BYTES 16384u

__device__ float g_h[2][HSZ*BSZ];
__device__ unsigned g_arrive;
__device__ unsigned g_release;

typedef unsigned long long ull;

__device__ __forceinline__ void unpack2(ull v, float &lo, float &hi){
    asm("mov.b64 {%0, %1}, %2;" : "=f"(lo), "=f"(hi) : "l"(v));
}
__device__ __forceinline__ void ffma2(ull &acc, ull a, ull b){
    asm("fma.rn.f32x2 %0, %1, %2, %0;" : "+l"(acc) : "l"(a), "l"(b));
}
__device__ __forceinline__ void addf2(ull &acc, ull a){
    asm("add.rn.f32x2 %0, %0, %1;" : "+l"(acc) : "l"(a));
}
__device__ __forceinline__ void cp16(uint32_t dst, const void* src){
    asm volatile("cp.async.cg.shared.global [%0], [%1], 16;" :: "r"(dst), "l"(src));
}
__device__ __forceinline__ float sigm(float x){
    return __fdividef(1.0f, 1.0f + __expf(-x));
}
__device__ __forceinline__ float ftanh(float x){
    float e = __expf(2.0f * x);
    return 1.0f - __fdividef(2.0f, e + 1.0f);
}

// 8-k slice of one chunk: 4 rows x 8 cols (16 f32x2 acc).
__device__ __forceinline__ void gemm_slice(const float* __restrict__ st,
                                           const float* __restrict__ wb,
                                           int c0, ull* __restrict__ acc)
{
    #pragma unroll
    for (int g = 0; g < 2; g++){
        ulonglong2 w0l = *(const ulonglong2*)(wb + 0*4*WCB_STR + g*8);
        ulonglong2 w0h = *(const ulonglong2*)(wb + 0*4*WCB_STR + g*8 + 4);
        ulonglong2 w1l = *(const ulonglong2*)(wb + 1*4*WCB_STR + g*8);
        ulonglong2 w1h = *(const ulonglong2*)(wb + 1*4*WCB_STR + g*8 + 4);
        ulonglong2 w2l = *(const ulonglong2*)(wb + 2*4*WCB_STR + g*8);
        ulonglong2 w2h = *(const ulonglong2*)(wb + 2*4*WCB_STR + g*8 + 4);
        ulonglong2 w3l = *(const ulonglong2*)(wb + 3*4*WCB_STR + g*8);
        ulonglong2 w3h = *(const ulonglong2*)(wb + 3*4*WCB_STR + g*8 + 4);
        #pragma unroll
        for (int kk = 0; kk < 4; kk++){
            const float* sp = st + (g*4 + kk)*64 + c0;
            ulonglong2 sa = *(const ulonglong2*)(sp);
            ulonglong2 sb = *(const ulonglong2*)(sp + 32);
            ull w0 = (kk==0)?w0l.x:(kk==1)?w0l.y:(kk==2)?w0h.x:w0h.y;
            ull w1 = (kk==0)?w1l.x:(kk==1)?w1l.y:(kk==2)?w1h.x:w1h.y;
            ull w2 = (kk==0)?w2l.x:(kk==1)?w2l.y:(kk==2)?w2h.x:w2h.y;
            ull w3 = (kk==0)?w3l.x:(kk==1)?w3l.y:(kk==2)?w3h.x:w3h.y;
            ffma2(acc[ 0], w0, sa.x); ffma2(acc[ 1], w0, sa.y);
            ffma2(acc[ 2], w0, sb.x); ffma2(acc[ 3], w0, sb.y);
            ffma2(acc[ 4], w1, sa.x); ffma2(acc[ 5], w1, sa.y);
            ffma2(acc[ 6], w1, sb.x); ffma2(acc[ 7], w1, sb.y);
            ffma2(acc[ 8], w2, sa.x); ffma2(acc[ 9], w2, sa.y);
            ffma2(acc[10], w2, sb.x); ffma2(acc[11], w2, sb.y);
            ffma2(acc[12], w3, sa.x); ffma2(acc[13], w3, sa.y);
            ffma2(acc[14], w3, sb.x); ffma2(acc[15], w3, sb.y);
        }
    }
}

extern "C" __global__ void __launch_bounds__(NTHR, 1)
lstm_bn_kernel(const float* __restrict__ x,
               const float* __restrict__ Wih,
               const float* __restrict__ Whh,
               const float* __restrict__ bias,
               const float* __restrict__ gIH, const float* __restrict__ bIH,
               const float* __restrict__ gHH, const float* __restrict__ bHH,
               const float* __restrict__ gC,  const float* __restrict__ bC,
               float* __restrict__ out, int T)
{
    extern __shared__ float sm[];
    float* wcb    = sm + OFF_WCB;
    float* stage  = sm + OFF_ST;
    float* sg     = sm + OFF_SG;
    float* ghh_s  = sm + OFF_CST;
    float* bhh_s  = ghh_s + 16;
    float* gih_s  = bhh_s + 16;
    float* bih_s  = gih_s + 16;
    float* bias_s = bih_s + 16;
    float* gc_s   = bias_s + 16;
    float* bc_s   = gc_s + 4;

    const int tid  = threadIdx.x;
    const int blk  = blockIdx.x;
    const int w    = tid >> 5;
    const int lane = tid & 31;
    const int rowg = lane >> 3;
    const int colg = lane & 7;
    const int c0   = colg * 4;

    // ---- preload combined weights, DUPLICATED: row = [ih 512 dup][hh 1024 dup][pad]
    for (int idx = tid; idx < 16*ISZ; idx += NTHR){
        int l = idx >> 8, k = idx & 255;
        int grow = (l >> 2) * HSZ + blk*4 + (l & 3);
        float v = Wih[(size_t)grow * ISZ + k];
        wcb[l*WCB_STR + 2*k]     = v;
        wcb[l*WCB_STR + 2*k + 1] = v;
    }
    for (int idx = tid; idx < 16*HSZ; idx += NTHR){
        int l = idx >> 9, k = idx & 511;
        int grow = (l >> 2) * HSZ + blk*4 + (l & 3);
        float v = Whh[(size_t)grow * HSZ + k];
        wcb[l*WCB_STR + 512 + 2*k]     = v;
        wcb[l*WCB_STR + 512 + 2*k + 1] = v;
    }
    if (tid < 16){
        int grow = (tid >> 2) * HSZ + blk*4 + (tid & 3);
        ghh_s[tid] = gHH[grow]; bhh_s[tid] = bHH[grow];
        gih_s[tid] = gIH[grow]; bih_s[tid] = bIH[grow];
        bias_s[tid] = bias[grow];
    }
    if (tid < 4){ gc_s[tid] = gC[blk*4 + tid]; bc_s[tid] = bC[blk*4 + tid]; }

    g_h[0][blk * NTHR + tid] = 0.f;
    __syncthreads();

    unsigned gen0 = 0, my_gen = 0;
    if (tid == 0) gen0 = *((volatile unsigned*)&g_release);

    auto gs_arrive = [&](){
        // caller guarantees a __syncthreads() already happened after the h writes
        if (tid == 0){
            my_gen++;
            __threadfence();
            unsigned a = atomicAdd(&g_arrive, 1u);
            if (a == (unsigned)(NBLK - 1)){
                atomicExch(&g_arrive, 0u);
                __threadfence();
                atomicAdd(&g_release, 1u);
            }
        }
    };
    auto gs_wait = [&](){
        if (tid == 0){
            while ( (*((volatile unsigned*)&g_release)) - gen0 < my_gen ) { }
        }
        __syncthreads();
    };

    const uint32_t stBase = (uint32_t)__cvta_generic_to_shared(stage);
    const float inv64 = 1.0f / 64.0f;
    float creg0 = 0.f, creg1 = 0.f;

    const float* wcbt = wcb + rowg*WCB_STR + w*16;   // + chunk*128 (x: 0..3, h: 4..11)

    auto issue_pair = [&](const float* cA, const float* cB, int sa, int sb){
        uint32_t dA = stBase + (uint32_t)sa * SLOT_BYTES;
        uint32_t dB = stBase + (uint32_t)sb * SLOT_BYTES;
        #pragma unroll
        for (int j = 0; j < 4; j++){
            cp16(dA + (uint32_t)(tid + j*256)*16u, cA + (tid + j*256)*4);
            cp16(dB + (uint32_t)(tid + j*256)*16u, cB + (tid + j*256)*4);
        }
        asm volatile("cp.async.commit_group;");
    };

    ull accB[16];
    #pragma unroll
    for (int i = 0; i < 16; i++) accB[i] = 0;

    // ---- prologue: stage + compute x GEMM of step 0 (independent of h)
    issue_pair(x,          x + 4096,   0, 1);
    issue_pair(x + 2*4096, x + 3*4096, 2, 3);
    asm volatile("cp.async.wait_group 0;");
    __syncthreads();
    #pragma unroll 1
    for (int cc = 0; cc < 4; cc++)
        gemm_slice(stage + cc*4096 + w*512, wcbt + cc*128, c0, accB);
    __syncthreads();          // x reads done before h prefetch reuses slots

    gs_arrive();              // also serves as step--1 arrive so wait() below pairs up
    gs_wait();                // h zeroed everywhere before step 0

    for (int t = 0; t < T; t++){
        const float* hrd = g_h[t & 1];
        float*       hwr = g_h[(t + 1) & 1];
        const float* xnx = x + (size_t)((t+1 < T) ? (t+1) : (T-1)) * (ISZ*BSZ);

        ull accA[16];
        #pragma unroll
        for (int i = 0; i < 16; i++) accA[i] = 0;

        // ---- h mainloop: 4 pairs. P0(s0,s1) P1(s2,s3) P2(s4,s5) P3(s0,s1)
        issue_pair(hrd,          hrd + 4096,   0, 1);
        issue_pair(hrd + 2*4096, hrd + 3*4096, 2, 3);
        issue_pair(hrd + 4*4096, hrd + 5*4096, 4, 5);

        // r0
        asm volatile("cp.async.wait_group 2;");
        __syncthreads();
        gemm_slice(stage + 0*4096 + w*512, wcbt + 4*128, c0, accA);
        gemm_slice(stage + 1*4096 + w*512, wcbt + 5*128, c0, accA);
        // r1
        asm volatile("cp.async.wait_group 1;");
        __syncthreads();
        issue_pair(hrd + 6*4096, hrd + 7*4096, 0, 1);
        gemm_slice(stage + 2*4096 + w*512, wcbt + 6*128, c0, accA);
        gemm_slice(stage + 3*4096 + w*512, wcbt + 7*128, c0, accA);
        // r2
        asm volatile("cp.async.wait_group 1;");
        __syncthreads();
        gemm_slice(stage + 4*4096 + w*512, wcbt + 8*128, c0, accA);
        gemm_slice(stage + 5*4096 + w*512, wcbt + 9*128, c0, accA);
        // r3
        asm volatile("cp.async.wait_group 0;");
        __syncthreads();
        gemm_slice(stage + 0*4096 + w*512, wcbt + 10*128, c0, accA);
        gemm_slice(stage + 1*4096 + w*512, wcbt + 11*128, c0, accA);

        __syncthreads();   // all slot reads done; entire ring = partial buffer
        float* pbufA = stage;                 // 8704 floats
        float* pbufB = stage + 8*16*PSTR;     // 8704 floats
        const int rr = tid >> 4, c4 = (tid & 15) * 4;
        float vA[4], vB[4];

        // ---- single-pass partial write (hh + ih), one barrier, one reduce
        {
            float* pa = pbufA + w*(16*PSTR);
            float* pb = pbufB + w*(16*PSTR);
            #pragma unroll
            for (int j = 0; j < 4; j++){
                int r2 = rowg + j*4;
                *(ulonglong2*)(pa + r2*PSTR + c0)      = make_ulonglong2(accA[j*4+0], accA[j*4+1]);
                *(ulonglong2*)(pa + r2*PSTR + c0 + 32) = make_ulonglong2(accA[j*4+2], accA[j*4+3]);
                *(ulonglong2*)(pb + r2*PSTR + c0)      = make_ulonglong2(accB[j*4+0], accB[j*4+1]);
                *(ulonglong2*)(pb + r2*PSTR + c0 + 32) = make_ulonglong2(accB[j*4+2], accB[j*4+3]);
            }
        }
        __syncthreads();
        {
            ulonglong2 s = *(const ulonglong2*)(pbufA + rr*PSTR + c4);
            ulonglong2 u = *(const ulonglong2*)(pbufB + rr*PSTR + c4);
            ull ax = s.x, ay = s.y, bx = u.x, by = u.y;
            #pragma unroll
            for (int ww = 1; ww < 8; ww++){
                ulonglong2 qa = *(const ulonglong2*)(pbufA + ww*(16*PSTR) + rr*PSTR + c4);
                ulonglong2 qb = *(const ulonglong2*)(pbufB + ww*(16*PSTR) + rr*PSTR + c4);
                addf2(ax, qa.x); addf2(ay, qa.y);
                addf2(bx, qb.x); addf2(by, qb.y);
            }
            unpack2(ax, vA[0], vA[1]); unpack2(ay, vA[2], vA[3]);
            unpack2(bx, vB[0], vB[1]); unpack2(by, vB[2], vB[3]);
        }
        __syncthreads();   // reduction reads done -> ring reusable

        // stage next-x into slots 0..3; consumed after arrive (below)
        issue_pair(xnx,          xnx + 4096,   0, 1);
        issue_pair(xnx + 2*4096, xnx + 3*4096, 2, 3);

        // ---- per-gate-row batchnorm
        {
            float sA = vA[0]+vA[1]+vA[2]+vA[3];
            float qA = vA[0]*vA[0]+vA[1]*vA[1]+vA[2]*vA[2]+vA[3]*vA[3];
            float sB = vB[0]+vB[1]+vB[2]+vB[3];
            float qB = vB[0]*vB[0]+vB[1]*vB[1]+vB[2]*vB[2]+vB[3]*vB[3];
            #pragma unroll
            for (int off = 1; off < 16; off <<= 1){
                sA += __shfl_xor_sync(0xffffffffu, sA, off);
                qA += __shfl_xor_sync(0xffffffffu, qA, off);
                sB += __shfl_xor_sync(0xffffffffu, sB, off);
                qB += __shfl_xor_sync(0xffffffffu, qB, off);
            }
            float muA = sA*inv64, muB = sB*inv64;
            float rsA = rsqrtf(qA*inv64 - muA*muA + EPSBN);
            float rsB = rsqrtf(qB*inv64 - muB*muB + EPSBN);
            float ga = ghh_s[rr]*rsA, gb = gih_s[rr]*rsB;
            float cadd = bhh_s[rr] + bih_s[rr] + bias_s[rr] - muA*ga - muB*gb;
            #pragma unroll
            for (int j = 0; j < 4; j++)
                sg[rr*64 + c4 + j] = fmaf(vA[j], ga, fmaf(vB[j], gb, cadd));
        }
        __syncthreads();   // sg published

        // ---- phase B: gates + cell + c-BN + h (warps 0-3)
        if (w < 4){
            float iv0 = sg[( 0 + w)*64 + lane], iv1 = sg[( 0 + w)*64 + lane + 32];
            float fv0 = sg[( 4 + w)*64 + lane], fv1 = sg[( 4 + w)*64 + lane + 32];
            float gv0 = sg[( 8 + w)*64 + lane], gv1 = sg[( 8 + w)*64 + lane + 32];
            float ov0 = sg[(12 + w)*64 + lane], ov1 = sg[(12 + w)*64 + lane + 32];

            creg0 = sigm(fv0)*creg0 + sigm(iv0)*ftanh(gv0);
            creg1 = sigm(fv1)*creg1 + sigm(iv1)*ftanh(gv1);

            float sc = creg0 + creg1;
            float qc = creg0*creg0 + creg1*creg1;
            #pragma unroll
            for (int off = 16; off >= 1; off >>= 1){
                sc += __shfl_xor_sync(0xffffffffu, sc, off);
                qc += __shfl_xor_sync(0xffffffffu, qc, off);
            }
            float mu = sc*inv64;
            float rs = rsqrtf(qc*inv64 - mu*mu + EPSBN);
            float gcv = gc_s[w]*rs;
            float bcv = bc_s[w] - mu*gcv;
            float h0v = sigm(ov0) * ftanh(fmaf(creg0, gcv, bcv));
            float h1v = sigm(ov1) * ftanh(fmaf(creg1, gcv, bcv));

            int rowg2 = blk*4 + w;
            hwr[rowg2*64 + lane]      = h0v;
            hwr[rowg2*64 + lane + 32] = h1v;
            float* op = out + (size_t)t * (HSZ*BSZ) + rowg2*64;
            op[lane]      = h0v;
            op[lane + 32] = h1v;
        }
        __syncthreads();   // h writes complete block-wide before arrive

        gs_arrive();       // signal our h slice is globally visible

        // ---- hide the release latency + inter-block skew: next step's x GEMM
        asm volatile("cp.async.wait_group 0;");
        __syncthreads();   // cross-warp staging visibility
        #pragma unroll
        for (int i = 0; i < 16; i++) accB[i] = 0;
        #pragma unroll 1
        for (int cc = 0; cc < 4; cc++)
            gemm_slice(stage + cc*4096 + w*512, wcbt + cc*128, c0, accB);

        gs_wait();         // all blocks' h visible; slots free for h prefetch
    }
}

extern "C" void kernel_launch(void* const* d_in, const int* in_sizes, int n_in,
                              void* d_out, int out_size)
{
    const float* x    = (const float*)d_in[0];
    const float* Wih  = (const float*)d_in[1];
    const float* Whh  = (const float*)d_in[2];
    const float* bias = (const float*)d_in[3];
    const float* gIH  = (const float*)d_in[4];
    const float* bIH  = (const float*)d_in[5];
    const float* gHH  = (const float*)d_in[6];
    const float* bHH  = (const float*)d_in[7];
    const float* gC   = (const float*)d_in[8];
    const float* bC   = (const float*)d_in[9];
    float* out = (float*)d_out;

    int T = in_sizes[0] / (ISZ * BSZ);   // 2048

    cudaFuncSetAttribute(lstm_bn_kernel,
                         cudaFuncAttributeMaxDynamicSharedMemorySize, SMEM_BYTES);
    lstm_bn_kernel<<<NBLK, NTHR, SMEM_BYTES>>>(x, Wih, Whh, bias,
                                               gIH, bIH, gHH, bHH, gC, bC,
                                               out, T);
}